// round 7
// baseline (speedup 1.0000x reference)
#include <cuda_runtime.h>
#include <cuda_fp16.h>
#include <cstdint>

#define TEMPERATURE 0.07f
constexpr int BSZ  = 256;
constexpr int MTOK = 128;
constexpr int DDIM = 768;

constexpr int KC     = 64;                 // K elements per smem stage (fp16)
constexpr int NCHUNK = DDIM / KC;          // 12
constexpr int PB     = 144;                // fp16 tile row pitch (128 data + 16 pad)
constexpr int TILE_B = 128 * PB;           // 18432 bytes per fp16 tile
constexpr int PB32   = 272;                // fp32 staging row pitch (256 data + 16 pad)
constexpr int B32_B  = 128 * PB32;         // 34816 bytes fp32 staging
// Layout: A16[0], B16[0], A16[1], B16[1], B32
constexpr int SMEM_TOTAL = 4 * TILE_B + B32_B;   // 108544 -> occ 2

// Scratch device globals (no allocation allowed anywhere)
__device__ float g_S[BSZ * BSZ];
__device__ float g_partial[BSZ];
__device__ unsigned g_count;
__device__ __align__(16) __half g_Ah[BSZ * DDIM];

// ---------------------------------------------------------------------------
__device__ __forceinline__ uint32_t smem_u32(const void* p) {
    uint32_t a;
    asm("{ .reg .u64 t; cvta.to.shared.u64 t, %1; cvt.u32.u64 %0, t; }"
        : "=r"(a) : "l"(p));
    return a;
}
__device__ __forceinline__ void cp_async16(uint32_t dst, const void* src) {
    asm volatile("cp.async.cg.shared.global [%0], [%1], 16;"
                 :: "r"(dst), "l"(src) : "memory");
}
#define CP_COMMIT() asm volatile("cp.async.commit_group;" ::: "memory")
#define CP_WAIT0()  asm volatile("cp.async.wait_group 0;" ::: "memory")

__device__ __forceinline__ void ldsm_x4(uint32_t* r, uint32_t addr) {
    asm volatile("ldmatrix.sync.aligned.m8n8.x4.shared.b16 {%0,%1,%2,%3}, [%4];"
                 : "=r"(r[0]), "=r"(r[1]), "=r"(r[2]), "=r"(r[3]) : "r"(addr));
}
__device__ __forceinline__ void mma_fp16(float* d, const uint32_t* a,
                                         const uint32_t* b) {
    asm volatile(
        "mma.sync.aligned.m16n8k16.row.col.f32.f16.f16.f32 "
        "{%0,%1,%2,%3}, {%4,%5,%6,%7}, {%8,%9}, {%0,%1,%2,%3};"
        : "+f"(d[0]), "+f"(d[1]), "+f"(d[2]), "+f"(d[3])
        : "r"(a[0]), "r"(a[1]), "r"(a[2]), "r"(a[3]), "r"(b[0]), "r"(b[1]));
}

// ---------------------------------------------------------------------------
// Kernel 0: convert V (fp32) to fp16 once; reset arrival counter.
// ---------------------------------------------------------------------------
__global__ void convert_a_kernel(const float* __restrict__ V) {
    int idx = blockIdx.x * blockDim.x + threadIdx.x;
    if (idx == 0) g_count = 0u;
    if (idx < BSZ * DDIM / 2) {
        float2 x = *(const float2*)(V + idx * 2);
        *(__half2*)(g_Ah + idx * 2) = __floats2half2_rn(x.x, x.y);
    }
}

// ---------------------------------------------------------------------------
// Kernel 1: single-product fp16 mma.sync GEMM + fused max over m.
// B staged as raw fp32 via cp.async BEFORE compute (latency hidden under the
// MMA stream), then a short smem->smem convert pass fills the fp16 tile.
// Grid (2, 256), 8 warps (4M x 2N), warp tile 32x64, occ 2.
// ---------------------------------------------------------------------------
__global__ __launch_bounds__(256, 2)
void gemm_max_mma(const float* __restrict__ T) {
    extern __shared__ char smem[];
    const uint32_t sbase = smem_u32(smem);
    const uint32_t b32u  = sbase + 4 * TILE_B;
    char* b32p = smem + 4 * TILE_B;
    const int tid  = threadIdx.x;
    const int lane = tid & 31;
    const int wid  = tid >> 5;
    const int warp_m = wid & 3;
    const int warp_n = wid >> 2;

    const int i0 = blockIdx.x * 128;
    const int j  = blockIdx.y;
    const float* __restrict__ Tj = T + (size_t)j * MTOK * DDIM;

    float acc[2][8][4];
#pragma unroll
    for (int mt = 0; mt < 2; mt++)
#pragma unroll
        for (int nt = 0; nt < 8; nt++)
#pragma unroll
            for (int e = 0; e < 4; e++) acc[mt][nt][e] = 0.0f;

    // ldmatrix lane offsets (tile-relative, bytes)
    const int q   = lane >> 3;
    const int idx = lane & 7;
    const uint32_t a_off = (uint32_t)((warp_m * 32 + ((q & 1) * 8 + idx)) * PB
                                      + (q >> 1) * 16);
    const uint32_t b_off = (uint32_t)((warp_n * 64 + ((q >> 1) * 8 + idx)) * PB
                                      + (q & 1) * 16);

    // A fill: cp.async of pre-converted fp16, 4 x 16B per thread.
    auto fill_A = [&](uint32_t stage_u32, int k0) {
#pragma unroll
        for (int p = 0; p < 4; p++) {
            const int u   = p * 256 + tid;
            const int row = u >> 3;
            const int ku  = u & 7;
            cp_async16(stage_u32 + (uint32_t)(row * PB + ku * 16),
                       g_Ah + (size_t)(i0 + row) * DDIM + k0 + ku * 8);
        }
    };
    // B stage: cp.async raw fp32 into B32 buffer, 8 x 16B per thread.
    auto stage_B32 = [&](int k0) {
#pragma unroll
        for (int p = 0; p < 8; p++) {
            const int u   = p * 256 + tid;
            const int row = u >> 4;
            const int kq4 = (u & 15) * 16;               // byte offset of float4
            cp_async16(b32u + (uint32_t)(row * PB32) + kq4,
                       Tj + (size_t)row * DDIM + k0 + (u & 15) * 4);
        }
    };
    // B convert: smem fp32 -> smem fp16 (short pass, no global latency).
    auto convert_B = [&](char* stage) {
        char* sB = stage + TILE_B;
#pragma unroll
        for (int p = 0; p < 8; p++) {
            const int u   = p * 256 + tid;
            const int row = u >> 4;
            const int kq  = (u & 15) * 4;
            const float4 b = *(const float4*)(b32p + row * PB32 + (u & 15) * 16);
            __half2 h01 = __floats2half2_rn(b.x, b.y);
            __half2 h23 = __floats2half2_rn(b.z, b.w);
            *(uint2*)(sB + row * PB + kq * 2) =
                make_uint2(*reinterpret_cast<unsigned*>(&h01),
                           *reinterpret_cast<unsigned*>(&h23));
        }
    };
    auto compute_chunk = [&](uint32_t sstage) {
#pragma unroll
        for (int ks = 0; ks < KC / 16; ks++) {
            uint32_t ah[2][4], bh[4][4];
#pragma unroll
            for (int mt = 0; mt < 2; mt++)
                ldsm_x4(ah[mt], sstage + a_off + mt * 16 * PB + ks * 32);
#pragma unroll
            for (int np = 0; np < 4; np++)
                ldsm_x4(bh[np], sstage + TILE_B + b_off + np * 16 * PB + ks * 32);
#pragma unroll
            for (int np = 0; np < 4; np++)
#pragma unroll
                for (int mt = 0; mt < 2; mt++) {
                    mma_fp16(acc[mt][2 * np],     ah[mt], bh[np]);
                    mma_fp16(acc[mt][2 * np + 1], ah[mt], bh[np] + 2);
                }
        }
    };

    // Prologue: chunk 0 -> stage 0.
    fill_A(sbase, 0);
    stage_B32(0);
    CP_COMMIT();
    CP_WAIT0();
    __syncthreads();
    convert_B(smem);            // B16[0]
    __syncthreads();

    for (int c = 0; c < NCHUNK; c++) {
        const int s = c & 1;
        if (c + 1 < NCHUNK) {
            // Prefetch next chunk: A fp16 + B fp32, all cp.async (latency
            // hidden under this chunk's MMAs).
            fill_A(sbase + (1 - s) * 2 * TILE_B, (c + 1) * KC);
            stage_B32((c + 1) * KC);
            CP_COMMIT();
        }
        compute_chunk(sbase + s * 2 * TILE_B);
        if (c + 1 < NCHUNK) {
            CP_WAIT0();
            __syncthreads();
            convert_B(smem + (1 - s) * 2 * TILE_B);   // short smem->smem pass
        }
        __syncthreads();
    }

    // Epilogue: max over the 128 m columns per i-row.
    float* buf = (float*)smem;   // [128][2]
#pragma unroll
    for (int mt = 0; mt < 2; mt++) {
        float mlo = -3.402823466e+38f, mhi = -3.402823466e+38f;
#pragma unroll
        for (int nt = 0; nt < 8; nt++) {
            mlo = fmaxf(mlo, fmaxf(acc[mt][nt][0], acc[mt][nt][1]));
            mhi = fmaxf(mhi, fmaxf(acc[mt][nt][2], acc[mt][nt][3]));
        }
        mlo = fmaxf(mlo, __shfl_xor_sync(0xffffffffu, mlo, 1));
        mlo = fmaxf(mlo, __shfl_xor_sync(0xffffffffu, mlo, 2));
        mhi = fmaxf(mhi, __shfl_xor_sync(0xffffffffu, mhi, 1));
        mhi = fmaxf(mhi, __shfl_xor_sync(0xffffffffu, mhi, 2));
        if ((lane & 3) == 0) {
            const int row = warp_m * 32 + mt * 16 + (lane >> 2);
            buf[row * 2 + warp_n]       = mlo;
            buf[(row + 8) * 2 + warp_n] = mhi;
        }
    }
    __syncthreads();
    if (tid < 128)
        g_S[(size_t)(i0 + tid) * BSZ + j] = fmaxf(buf[tid * 2], buf[tid * 2 + 1]);
}

// ---------------------------------------------------------------------------
// Kernel 2: per-index LSE terms; last block also does the final reduction
// (threadfence-reduction pattern; deterministic fixed-order single-block sum).
// ---------------------------------------------------------------------------
__global__ void lse_finalize_kernel(float* __restrict__ out) {
    __shared__ float sm[BSZ];
    __shared__ unsigned is_last;
    const int i = blockIdx.x;
    const int t = threadIdx.x;

    const float rv   = g_S[(size_t)i * BSZ + t];
    const float cv   = g_S[(size_t)t * BSZ + i];
    const float diag = g_S[(size_t)i * BSZ + i] * (1.0f / TEMPERATURE);

    sm[t] = rv; __syncthreads();
    for (int s = 128; s >= 1; s >>= 1) {
        if (t < s) sm[t] = fmaxf(sm[t], sm[t + s]);
        __syncthreads();
    }
    const float rmax = sm[0]; __syncthreads();
    sm[t] = expf((rv - rmax) * (1.0f / TEMPERATURE)); __syncthreads();
    for (int s = 128; s >= 1; s >>= 1) {
        if (t < s) sm[t] += sm[t + s];
        __syncthreads();
    }
    const float rsum = sm[0]; __syncthreads();

    sm[t] = cv; __syncthreads();
    for (int s = 128; s >= 1; s >>= 1) {
        if (t < s) sm[t] = fmaxf(sm[t], sm[t + s]);
        __syncthreads();
    }
    const float cmax = sm[0]; __syncthreads();
    sm[t] = expf((cv - cmax) * (1.0f / TEMPERATURE)); __syncthreads();
    for (int s = 128; s >= 1; s >>= 1) {
        if (t < s) sm[t] += sm[t + s];
        __syncthreads();
    }
    const float csum = sm[0];

    if (t == 0) {
        const float lse_r = rmax * (1.0f / TEMPERATURE) + logf(rsum);
        const float lse_c = cmax * (1.0f / TEMPERATURE) + logf(csum);
        g_partial[i] = (lse_r - diag) + (lse_c - diag);
        __threadfence();
        unsigned done = atomicAdd(&g_count, 1u);
        is_last = (done == (unsigned)(BSZ - 1)) ? 1u : 0u;
    }
    __syncthreads();

    if (is_last) {
        __threadfence();                 // make all g_partial writes visible
        sm[t] = g_partial[t]; __syncthreads();
        for (int s = 128; s >= 1; s >>= 1) {
            if (t < s) sm[t] += sm[t + s];
            __syncthreads();
        }
        if (t == 0) out[0] = sm[0] * (1.0f / (2.0f * (float)BSZ));
    }
}

// ---------------------------------------------------------------------------
extern "C" void kernel_launch(void* const* d_in, const int* in_sizes, int n_in,
                              void* d_out, int out_size) {
    const float* V = (const float*)d_in[0];  // v_final [256, 768]
    const float* T = (const float*)d_in[1];  // T_fused [256, 128, 768]
    float* out = (float*)d_out;

    cudaFuncSetAttribute(gemm_max_mma, cudaFuncAttributeMaxDynamicSharedMemorySize,
                         SMEM_TOTAL);

    convert_a_kernel<<<(BSZ * DDIM / 2 + 255) / 256, 256>>>(V);
    gemm_max_mma<<<dim3(2, BSZ), 256, SMEM_TOTAL>>>(T);
    lse_finalize_kernel<<<BSZ, BSZ>>>(out);
}

// round 8
// speedup vs baseline: 1.1555x; 1.1555x over previous
#include <cuda_runtime.h>
#include <cuda_fp16.h>
#include <cstdint>

#define TEMPERATURE 0.07f
constexpr int BSZ  = 256;
constexpr int MTOK = 128;
constexpr int DDIM = 768;

constexpr int KC     = 64;                 // K elements per smem stage (fp16)
constexpr int NCHUNK = DDIM / KC;          // 12
constexpr int PB     = 144;                // smem row pitch bytes (128 data + 16 pad)
constexpr int TILE_B = 128 * PB;           // 18432 bytes per tile
constexpr int STAGE_B = 2 * TILE_B;        // A, B (single fp16 product)
constexpr int SMEM_TOTAL = 2 * STAGE_B;    // 73728, double buffered -> occ 2

// Scratch device globals (no allocation allowed anywhere)
__device__ float g_S[BSZ * BSZ];
__device__ float g_partial[BSZ];
__device__ unsigned g_count;
__device__ __align__(16) __half g_Ah[BSZ * DDIM];

// ---------------------------------------------------------------------------
__device__ __forceinline__ uint32_t smem_u32(const void* p) {
    uint32_t a;
    asm("{ .reg .u64 t; cvta.to.shared.u64 t, %1; cvt.u32.u64 %0, t; }"
        : "=r"(a) : "l"(p));
    return a;
}
__device__ __forceinline__ void cp_async16(uint32_t dst, const void* src) {
    asm volatile("cp.async.cg.shared.global [%0], [%1], 16;"
                 :: "r"(dst), "l"(src) : "memory");
}
#define CP_COMMIT() asm volatile("cp.async.commit_group;" ::: "memory")
#define CP_WAIT0()  asm volatile("cp.async.wait_group 0;" ::: "memory")

__device__ __forceinline__ void ldsm_x4(uint32_t* r, uint32_t addr) {
    asm volatile("ldmatrix.sync.aligned.m8n8.x4.shared.b16 {%0,%1,%2,%3}, [%4];"
                 : "=r"(r[0]), "=r"(r[1]), "=r"(r[2]), "=r"(r[3]) : "r"(addr));
}
__device__ __forceinline__ void mma_fp16(float* d, const uint32_t* a,
                                         const uint32_t* b) {
    asm volatile(
        "mma.sync.aligned.m16n8k16.row.col.f32.f16.f16.f32 "
        "{%0,%1,%2,%3}, {%4,%5,%6,%7}, {%8,%9}, {%0,%1,%2,%3};"
        : "+f"(d[0]), "+f"(d[1]), "+f"(d[2]), "+f"(d[3])
        : "r"(a[0]), "r"(a[1]), "r"(a[2]), "r"(a[3]), "r"(b[0]), "r"(b[1]));
}

// ---------------------------------------------------------------------------
// Kernel 0: convert V (fp32) to fp16 once; reset arrival counter.
// ---------------------------------------------------------------------------
__global__ void convert_a_kernel(const float* __restrict__ V) {
    int idx = blockIdx.x * blockDim.x + threadIdx.x;
    if (idx == 0) g_count = 0u;
    if (idx < BSZ * DDIM / 2) {
        float2 x = *(const float2*)(V + idx * 2);
        *(__half2*)(g_Ah + idx * 2) = __floats2half2_rn(x.x, x.y);
    }
}

// ---------------------------------------------------------------------------
// Kernel 1: single-product fp16 mma.sync GEMM + fused max over m.
// D = fp16(A) . fp16(B), fp32 accumulate.
// Grid (2, 256), 8 warps (4M x 2N), warp tile 32x64, occ 2.
// A staged via cp.async (pre-converted fp16). B: LDGs for the NEXT chunk are
// issued BEFORE this chunk's MMAs (register prefetch, latency hidden under
// the tensor stream); cvt+STS run after compute with data already in regs.
// ---------------------------------------------------------------------------
__global__ __launch_bounds__(256, 2)
void gemm_max_mma(const float* __restrict__ T) {
    extern __shared__ char smem[];
    const uint32_t sbase = smem_u32(smem);
    const int tid  = threadIdx.x;
    const int lane = tid & 31;
    const int wid  = tid >> 5;
    const int warp_m = wid & 3;
    const int warp_n = wid >> 2;

    const int i0 = blockIdx.x * 128;
    const int j  = blockIdx.y;
    const float* __restrict__ Tj = T + (size_t)j * MTOK * DDIM;

    float acc[2][8][4];
#pragma unroll
    for (int mt = 0; mt < 2; mt++)
#pragma unroll
        for (int nt = 0; nt < 8; nt++)
#pragma unroll
            for (int e = 0; e < 4; e++) acc[mt][nt][e] = 0.0f;

    // ldmatrix lane offsets (tile-relative, bytes)
    const int q   = lane >> 3;
    const int idx = lane & 7;
    const uint32_t a_off = (uint32_t)((warp_m * 32 + ((q & 1) * 8 + idx)) * PB
                                      + (q >> 1) * 16);
    const uint32_t b_off = (uint32_t)((warp_n * 64 + ((q >> 1) * 8 + idx)) * PB
                                      + (q & 1) * 16);

    float4 br[8];   // B register prefetch (fp32)

    // A fill: cp.async, 4 x 16B per thread.
    auto fill_A = [&](uint32_t stage_u32, int k0) {
#pragma unroll
        for (int p = 0; p < 4; p++) {
            const int u   = p * 256 + tid;
            const int row = u >> 3;
            const int ku  = u & 7;
            cp_async16(stage_u32 + (uint32_t)(row * PB + ku * 16),
                       g_Ah + (size_t)(i0 + row) * DDIM + k0 + ku * 8);
        }
    };
    // B LDG: 8 float4 per thread into registers (issued before compute).
    auto ldg_B = [&](int k0) {
#pragma unroll
        for (int p = 0; p < 8; p++) {
            const int u = p * 256 + tid;
            br[p] = *(const float4*)(Tj + (size_t)(u >> 4) * DDIM + k0 + (u & 15) * 4);
        }
    };
    // B STS: cvt fp32->fp16 from registers, no memory wait.
    auto sts_B = [&](char* stage) {
        char* sB = stage + TILE_B;
#pragma unroll
        for (int p = 0; p < 8; p++) {
            const int u   = p * 256 + tid;
            const int row = u >> 4;
            const int kq  = (u & 15) * 4;
            const float4 b = br[p];
            __half2 h01 = __floats2half2_rn(b.x, b.y);
            __half2 h23 = __floats2half2_rn(b.z, b.w);
            *(uint2*)(sB + row * PB + kq * 2) =
                make_uint2(*reinterpret_cast<unsigned*>(&h01),
                           *reinterpret_cast<unsigned*>(&h23));
        }
    };
    auto compute_chunk = [&](uint32_t sstage) {
#pragma unroll
        for (int ks = 0; ks < KC / 16; ks++) {
            uint32_t ah[2][4], bh[4][4];
#pragma unroll
            for (int mt = 0; mt < 2; mt++)
                ldsm_x4(ah[mt], sstage + a_off + mt * 16 * PB + ks * 32);
#pragma unroll
            for (int np = 0; np < 4; np++)
                ldsm_x4(bh[np], sstage + TILE_B + b_off + np * 16 * PB + ks * 32);
#pragma unroll
            for (int np = 0; np < 4; np++)
#pragma unroll
                for (int mt = 0; mt < 2; mt++) {
                    mma_fp16(acc[mt][2 * np],     ah[mt], bh[np]);
                    mma_fp16(acc[mt][2 * np + 1], ah[mt], bh[np] + 2);
                }
        }
    };

    // Prologue: chunk 0 -> stage 0.
    ldg_B(0);
    fill_A(sbase, 0);
    CP_COMMIT();
    sts_B(smem);
    CP_WAIT0();
    __syncthreads();

    for (int c = 0; c < NCHUNK; c++) {
        const int s = c & 1;
        if (c + 1 < NCHUNK) {
            ldg_B((c + 1) * KC);                              // LDG latency ->
            fill_A(sbase + (1 - s) * STAGE_B, (c + 1) * KC);  // hidden under
            CP_COMMIT();                                      // the MMA stream
        }
        compute_chunk(sbase + s * STAGE_B);
        if (c + 1 < NCHUNK) {
            sts_B(smem + (1 - s) * STAGE_B);                  // regs -> smem
            CP_WAIT0();
        }
        __syncthreads();
    }

    // Epilogue: max over the 128 m columns per i-row.
    float* buf = (float*)smem;   // [128][2]
#pragma unroll
    for (int mt = 0; mt < 2; mt++) {
        float mlo = -3.402823466e+38f, mhi = -3.402823466e+38f;
#pragma unroll
        for (int nt = 0; nt < 8; nt++) {
            mlo = fmaxf(mlo, fmaxf(acc[mt][nt][0], acc[mt][nt][1]));
            mhi = fmaxf(mhi, fmaxf(acc[mt][nt][2], acc[mt][nt][3]));
        }
        mlo = fmaxf(mlo, __shfl_xor_sync(0xffffffffu, mlo, 1));
        mlo = fmaxf(mlo, __shfl_xor_sync(0xffffffffu, mlo, 2));
        mhi = fmaxf(mhi, __shfl_xor_sync(0xffffffffu, mhi, 1));
        mhi = fmaxf(mhi, __shfl_xor_sync(0xffffffffu, mhi, 2));
        if ((lane & 3) == 0) {
            const int row = warp_m * 32 + mt * 16 + (lane >> 2);
            buf[row * 2 + warp_n]       = mlo;
            buf[(row + 8) * 2 + warp_n] = mhi;
        }
    }
    __syncthreads();
    if (tid < 128)
        g_S[(size_t)(i0 + tid) * BSZ + j] = fmaxf(buf[tid * 2], buf[tid * 2 + 1]);
}

// ---------------------------------------------------------------------------
// Kernel 2: per-index LSE terms; last block also does the final reduction
// (threadfence-reduction pattern; deterministic fixed-order single-block sum).
// ---------------------------------------------------------------------------
__global__ void lse_finalize_kernel(float* __restrict__ out) {
    __shared__ float sm[BSZ];
    __shared__ unsigned is_last;
    const int i = blockIdx.x;
    const int t = threadIdx.x;

    const float rv   = g_S[(size_t)i * BSZ + t];
    const float cv   = g_S[(size_t)t * BSZ + i];
    const float diag = g_S[(size_t)i * BSZ + i] * (1.0f / TEMPERATURE);

    sm[t] = rv; __syncthreads();
    for (int s = 128; s >= 1; s >>= 1) {
        if (t < s) sm[t] = fmaxf(sm[t], sm[t + s]);
        __syncthreads();
    }
    const float rmax = sm[0]; __syncthreads();
    sm[t] = expf((rv - rmax) * (1.0f / TEMPERATURE)); __syncthreads();
    for (int s = 128; s >= 1; s >>= 1) {
        if (t < s) sm[t] += sm[t + s];
        __syncthreads();
    }
    const float rsum = sm[0]; __syncthreads();

    sm[t] = cv; __syncthreads();
    for (int s = 128; s >= 1; s >>= 1) {
        if (t < s) sm[t] = fmaxf(sm[t], sm[t + s]);
        __syncthreads();
    }
    const float cmax = sm[0]; __syncthreads();
    sm[t] = expf((cv - cmax) * (1.0f / TEMPERATURE)); __syncthreads();
    for (int s = 128; s >= 1; s >>= 1) {
        if (t < s) sm[t] += sm[t + s];
        __syncthreads();
    }
    const float csum = sm[0];

    if (t == 0) {
        const float lse_r = rmax * (1.0f / TEMPERATURE) + logf(rsum);
        const float lse_c = cmax * (1.0f / TEMPERATURE) + logf(csum);
        g_partial[i] = (lse_r - diag) + (lse_c - diag);
        __threadfence();
        unsigned done = atomicAdd(&g_count, 1u);
        is_last = (done == (unsigned)(BSZ - 1)) ? 1u : 0u;
    }
    __syncthreads();

    if (is_last) {
        __threadfence();                 // make all g_partial writes visible
        sm[t] = g_partial[t]; __syncthreads();
        for (int s = 128; s >= 1; s >>= 1) {
            if (t < s) sm[t] += sm[t + s];
            __syncthreads();
        }
        if (t == 0) out[0] = sm[0] * (1.0f / (2.0f * (float)BSZ));
    }
}

// ---------------------------------------------------------------------------
extern "C" void kernel_launch(void* const* d_in, const int* in_sizes, int n_in,
                              void* d_out, int out_size) {
    const float* V = (const float*)d_in[0];  // v_final [256, 768]
    const float* T = (const float*)d_in[1];  // T_fused [256, 128, 768]
    float* out = (float*)d_out;

    cudaFuncSetAttribute(gemm_max_mma, cudaFuncAttributeMaxDynamicSharedMemorySize,
                         SMEM_TOTAL);

    convert_a_kernel<<<(BSZ * DDIM / 2 + 255) / 256, 256>>>(V);
    gemm_max_mma<<<dim3(2, BSZ), 256, SMEM_TOTAL>>>(T);
    lse_finalize_kernel<<<BSZ, BSZ>>>(out);
}